// round 15
// baseline (speedup 1.0000x reference)
#include <cuda_runtime.h>
#include <cuda_fp16.h>
#include <cstdint>

// IndRNN on GB300 (compute_103 target -> mma.sync HMMA):
//   proj = fp16(x) @ fp16(W) + b   (single-term; rel_err ~2.4e-4, gate 1e-3)
//   h_t  = relu(proj_t + h_{t-1} * clip(u,0,1))  scan in-place on d_out
//
// GEMM: 64Mx128N CTA tiles (2048 CTAs -> 6.92 waves on 296 slots, ~99% wave eff).
// x loaded fp32 into smem, A-frags built in registers (LDS.64 + cvt).
//
// Inputs: x [64,512,256] f32, h0 [64,512] f32, W [256,512] f32, u [512] f32, b [512] f32.
// Output [64,512,512] f32.

#define BATCH 64
#define TT    512
#define DD    256
#define UU    512
#define MM    (BATCH * TT)      // 32768

// ---------------- device scratch ----------------
__device__ __align__(16) __half g_Bt[(size_t)UU * DD];   // 256 KB [n][k] (W^T, fp16)

// ---------------- PTX helpers (baseline <= sm_80) ----------------
__device__ __forceinline__ uint32_t smem_u32(const void* p) {
    uint32_t a;
    asm("{ .reg .u64 t; cvta.to.shared.u64 t, %1; cvt.u32.u64 %0, t; }" : "=r"(a) : "l"(p));
    return a;
}
#define CP16(dst, src) \
    asm volatile("cp.async.cg.shared.global [%0], [%1], 16;" :: "r"(dst), "l"(src) : "memory")
#define CP_COMMIT() asm volatile("cp.async.commit_group;" ::: "memory")
#define CP_WAITN(n) asm volatile("cp.async.wait_group %0;" :: "n"(n) : "memory")

#define LDSM_X4(r0, r1, r2, r3, addr) \
    asm volatile("ldmatrix.sync.aligned.m8n8.x4.shared.b16 {%0,%1,%2,%3}, [%4];" \
        : "=r"(r0), "=r"(r1), "=r"(r2), "=r"(r3) : "r"(addr))

#define LDS64F(x, y, addr) \
    asm volatile("ld.shared.v2.f32 {%0,%1}, [%2];" : "=f"(x), "=f"(y) : "r"(addr))

#define MMA_F16(d, a, b0, b1) \
    asm volatile("mma.sync.aligned.m16n8k16.row.col.f32.f16.f16.f32 " \
        "{%0,%1,%2,%3}, {%4,%5,%6,%7}, {%8,%9}, {%0,%1,%2,%3};" \
        : "+f"((d)[0]), "+f"((d)[1]), "+f"((d)[2]), "+f"((d)[3]) \
        : "r"((a)[0]), "r"((a)[1]), "r"((a)[2]), "r"((a)[3]), "r"(b0), "r"(b1))

__device__ __forceinline__ uint32_t f2h2(float lo, float hi) {
    __half2 h = __floats2half2_rn(lo, hi);
    return *reinterpret_cast<uint32_t*>(&h);
}

// ---------------- prep: fp16 + transpose W via smem tiles ----------------
// Block handles a 32k x 64n tile. Coalesced float4 reads, 16B transposed writes.
__global__ __launch_bounds__(256) void convert_w(const float* __restrict__ W) {
    __shared__ float tile[32][65];
    const int k0 = blockIdx.x * 32;       // 8 blocks in k
    const int n0 = blockIdx.y * 64;       // 8 blocks in n
    const int tid = threadIdx.x;

    // read: 32 rows x 16 float4 = 512 float4, 2 per thread
#pragma unroll
    for (int r = 0; r < 2; r++) {
        int idx = tid + r * 256;
        int k = idx >> 4;                 // 0..31
        int n4 = (idx & 15) << 2;         // 0..60
        float4 v = *reinterpret_cast<const float4*>(W + (size_t)(k0 + k) * UU + n0 + n4);
        tile[k][n4 + 0] = v.x;
        tile[k][n4 + 1] = v.y;
        tile[k][n4 + 2] = v.z;
        tile[k][n4 + 3] = v.w;
    }
    __syncthreads();

    // write: 64 n-rows x 32 k halves; thread = (n, kgroup of 8) -> one 16B store
    const int n = tid >> 2;               // 0..63
    const int kg = (tid & 3) << 3;        // 0,8,16,24
    __half2 h[4];
#pragma unroll
    for (int i = 0; i < 4; i++)
        h[i] = __floats2half2_rn(tile[kg + 2 * i][n], tile[kg + 2 * i + 1][n]);
    *reinterpret_cast<uint4*>(g_Bt + (size_t)(n0 + n) * DD + k0 + kg) =
        *reinterpret_cast<uint4*>(h);
}

// ---------------- GEMM via mma.sync ----------------
// CTA 64(M) x 128(N), K-chunk 32, 3-stage cp.async ring, 8 warps (2m x 4n),
// warp tile 32x32 (mt=2, nt=4) -> 8 independent accumulators innermost.
#define ROWA      160                          // bytes per A smem row (32 floats + pad)
#define ABUF      (64 * ROWA)                  // 10240 B
#define ROWB      80
#define BBUF      (128 * ROWB)                 // 10240 B
#define OFF_B     ABUF
#define STAGE_SZ  (ABUF + BBUF)                // 20480 B
#define NSTAGE    3
#define SM_TOTAL  (NSTAGE * STAGE_SZ)          // 61440 B

__device__ __forceinline__ void load_chunk(uint32_t stage_base, const char* gx,
                                           int bm, int bn, int k0, int tid) {
    const char* gB = reinterpret_cast<const char*>(g_Bt);
    // A: fp32, 64 rows x 128 B -> 512 cp16 (2 per thread)
#pragma unroll
    for (int r = 0; r < 2; r++) {
        int idx = tid + r * 256;
        int row = idx >> 3;
        int seg = (idx & 7) << 4;
        CP16(stage_base + row * ROWA + seg,
             gx + (size_t)(bm + row) * 1024 + k0 * 4 + seg);
    }
    // B: fp16, 128 rows x 64 B -> 512 cp16 (2 per thread)
#pragma unroll
    for (int r = 0; r < 2; r++) {
        int idx = tid + r * 256;
        int row = idx >> 2;
        int seg = (idx & 3) << 4;
        CP16(stage_base + OFF_B + row * ROWB + seg,
             gB + (size_t)(bn + row) * 512 + k0 * 2 + seg);
    }
}

__global__ __launch_bounds__(256, 2) void indrnn_gemm_mma(
    const float* __restrict__ X, const float* __restrict__ bias, float* __restrict__ C)
{
    extern __shared__ char smem[];
    const uint32_t sbase = smem_u32(smem);
    const char* gx = reinterpret_cast<const char*>(X);
    const int tid  = threadIdx.x;
    const int wid  = tid >> 5;
    const int lane = tid & 31;
    const int bm   = blockIdx.y * 64;
    const int bn   = blockIdx.x * 128;
    const int wm   = (wid & 1) * 32;      // 2 m-warps
    const int wn   = (wid >> 1) * 32;     // 4 n-warps

    float acc[2][4][4];
#pragma unroll
    for (int mt = 0; mt < 2; mt++)
#pragma unroll
        for (int nt = 0; nt < 4; nt++)
#pragma unroll
            for (int i = 0; i < 4; i++) acc[mt][nt][i] = 0.0f;

    load_chunk(sbase,            gx, bm, bn, 0,  tid); CP_COMMIT();
    load_chunk(sbase + STAGE_SZ, gx, bm, bn, 32, tid); CP_COMMIT();

    // A-frag addressing (fp32 smem): row = wm + mt*16 + g (+8), col = 2t (+1, +8)
    const int g = lane >> 2;
    const int t = lane & 3;
    const uint32_t a_base = (wm + g) * ROWA + t * 8;
    // B ldmatrix x4 covers an nt-pair (16 n-rows) x 16 k
    const uint32_t b_base = (wn + ((lane >> 4) & 1) * 8 + (lane & 7)) * ROWB
                          + ((lane >> 3) & 1) * 16;

    int stage = 0;
    for (int c = 0; c < 8; c++) {
        if (c < 7) { CP_WAITN(1); } else { CP_WAITN(0); }
        __syncthreads();   // chunk c visible; all warps vacated stage of chunk c-1

        if (c + 2 < 8) {
            int ns = stage + 2; if (ns >= NSTAGE) ns -= NSTAGE;
            load_chunk(sbase + ns * STAGE_SZ, gx, bm, bn, (c + 2) * 32, tid);
            CP_COMMIT();
        }

        const uint32_t aSm = sbase + stage * STAGE_SZ;
        const uint32_t bSm = aSm + OFF_B;

#pragma unroll
        for (int k16 = 0; k16 < 2; k16++) {
            const uint32_t kbA = k16 * 64;
            const uint32_t kbB = k16 * 32;

            uint32_t af[2][4];
#pragma unroll
            for (int mt = 0; mt < 2; mt++) {
                const uint32_t ab = aSm + a_base + mt * (16 * ROWA) + kbA;
                float x0, y0, x1, y1, x2, y2, x3, y3;
                LDS64F(x0, y0, ab);
                LDS64F(x1, y1, ab + 8 * ROWA);
                LDS64F(x2, y2, ab + 32);
                LDS64F(x3, y3, ab + 8 * ROWA + 32);
                af[mt][0] = f2h2(x0, y0);
                af[mt][1] = f2h2(x1, y1);
                af[mt][2] = f2h2(x2, y2);
                af[mt][3] = f2h2(x3, y3);
            }

            uint32_t bf[4][2];
#pragma unroll
            for (int np = 0; np < 2; np++)
                LDSM_X4(bf[2 * np][0], bf[2 * np][1], bf[2 * np + 1][0], bf[2 * np + 1][1],
                        bSm + b_base + np * (16 * ROWB) + kbB);

            // 8 independent accumulators back-to-back
#pragma unroll
            for (int nt = 0; nt < 4; nt++) {
                MMA_F16(acc[0][nt], af[0], bf[nt][0], bf[nt][1]);
                MMA_F16(acc[1][nt], af[1], bf[nt][0], bf[nt][1]);
            }
        }

        if (++stage == NSTAGE) stage = 0;
    }

    // epilogue: c-frag thread holds (m = lane/4 [+8], n = (lane%4)*2 [+1])
    const int m0   = bm + wm + (lane >> 2);
    const int col0 = bn + wn + (lane & 3) * 2;
#pragma unroll
    for (int mt = 0; mt < 2; mt++) {
#pragma unroll
        for (int nt = 0; nt < 4; nt++) {
            const int r = m0 + mt * 16;
            const int cc = col0 + nt * 8;
            const float2 bv = *reinterpret_cast<const float2*>(bias + cc);
            float2 o0, o1;
            o0.x = acc[mt][nt][0] + bv.x;
            o0.y = acc[mt][nt][1] + bv.y;
            o1.x = acc[mt][nt][2] + bv.x;
            o1.y = acc[mt][nt][3] + bv.y;
            *reinterpret_cast<float2*>(C + (size_t)r * UU + cc)       = o0;
            *reinterpret_cast<float2*>(C + (size_t)(r + 8) * UU + cc) = o1;
        }
    }
}

// ---------------- scan: cp.async smem ring (8 stages x 16 timesteps) ----------------
#define SC_TS    16
#define SC_NS    8
#define SC_STAGE (SC_TS * 128 * 4)          // 8192 B
#define SC_SMEM  (SC_NS * SC_STAGE)         // 65536 B

__device__ __forceinline__ void scan_issue_stage(uint32_t sm_stage, const char* gbase,
                                                 int t0, int tid) {
#pragma unroll
    for (int k = 0; k < 4; k++) {
        int j = tid + k * 128;              // 0..511
        int t = j >> 5;
        int seg = (j & 31) << 4;            // 16B chunks across 512B row
        CP16(sm_stage + t * 512 + seg, gbase + (size_t)(t0 + t) * (UU * 4) + seg);
    }
}

__global__ __launch_bounds__(128) void indrnn_scan(
    const float* __restrict__ h0,
    const float* __restrict__ u,
    float* __restrict__ out)
{
    extern __shared__ float sbuf[];
    const uint32_t sm = smem_u32(sbuf);
    const int tid = threadIdx.x;
    const int u0  = (blockIdx.x & 3) * 128;
    const int bb  = blockIdx.x >> 2;
    const int uu  = u0 + tid;

    const float uc = fminf(fmaxf(u[uu], 0.0f), 1.0f);
    float h = h0[bb * UU + uu];

    float* pout = out + (size_t)bb * TT * UU + uu;
    const char* gbase = reinterpret_cast<const char*>(out)
                      + ((size_t)bb * TT * UU + u0) * 4;

#pragma unroll
    for (int s = 0; s < SC_NS - 1; s++) {
        scan_issue_stage(sm + s * SC_STAGE, gbase, s * SC_TS, tid);
        CP_COMMIT();
    }

#pragma unroll 1
    for (int blk = 0; blk < TT / SC_TS; blk++) {
        CP_WAITN(SC_NS - 2);
        __syncthreads();

        const int nb = blk + SC_NS - 1;
        if (nb < TT / SC_TS) {
            scan_issue_stage(sm + (nb & (SC_NS - 1)) * SC_STAGE, gbase, nb * SC_TS, tid);
        }
        CP_COMMIT();

        const float* stage = sbuf + (blk & (SC_NS - 1)) * (SC_TS * 128) + tid;
        const int t0 = blk * SC_TS;
#pragma unroll
        for (int i = 0; i < SC_TS; i++) {
            h = fmaxf(fmaf(h, uc, stage[i * 128]), 0.0f);
            pout[(size_t)(t0 + i) * UU] = h;
        }
    }
}

extern "C" void kernel_launch(void* const* d_in, const int* in_sizes, int n_in,
                              void* d_out, int out_size)
{
    const float* x  = (const float*)d_in[0];
    const float* h0 = (const float*)d_in[1];
    const float* W  = (const float*)d_in[2];
    const float* u  = (const float*)d_in[3];
    const float* b  = (const float*)d_in[4];
    float* out = (float*)d_out;

    cudaFuncSetAttribute(indrnn_gemm_mma, cudaFuncAttributeMaxDynamicSharedMemorySize, SM_TOTAL);
    cudaFuncSetAttribute(indrnn_scan,     cudaFuncAttributeMaxDynamicSharedMemorySize, SC_SMEM);

    dim3 wgrid(DD / 32, UU / 64);    // (8, 8)
    convert_w<<<wgrid, 256>>>(W);

    dim3 grid(UU / 128, MM / 64);    // (4, 512) = 2048 CTAs
    indrnn_gemm_mma<<<grid, 256, SM_TOTAL>>>(x, b, out);

    indrnn_scan<<<(BATCH * UU) / 128, 128, SC_SMEM>>>(h0, u, out);
}

// round 16
// speedup vs baseline: 1.0910x; 1.0910x over previous
#include <cuda_runtime.h>
#include <cuda_fp16.h>
#include <cstdint>

// IndRNN on GB300 (compute_103 target -> mma.sync HMMA):
//   proj = fp16(x) @ fp16(W) + b   stored as fp16 scratch (32 MB)
//   h_t  = relu(proj_t + h_{t-1} * clip(u,0,1))  -> fp32 d_out
//
// GEMM: R13-proven 128x128 CTA tile, 3-stage cp.async ring, 2 CTA/SM.
// x loaded fp32 into smem, A-frags built in registers (LDS.64 + cvt).
//
// Inputs: x [64,512,256] f32, h0 [64,512] f32, W [256,512] f32, u [512] f32, b [512] f32.
// Output [64,512,512] f32.

#define BATCH 64
#define TT    512
#define DD    256
#define UU    512
#define MM    (BATCH * TT)      // 32768

// ---------------- device scratch ----------------
__device__ __align__(16) __half g_Bt[(size_t)UU * DD];     // 256 KB [n][k] (W^T, fp16)
__device__ __align__(16) __half g_proj[(size_t)MM * UU];   // 32 MB  [m][n] fp16 proj

// ---------------- PTX helpers (baseline <= sm_80) ----------------
__device__ __forceinline__ uint32_t smem_u32(const void* p) {
    uint32_t a;
    asm("{ .reg .u64 t; cvta.to.shared.u64 t, %1; cvt.u32.u64 %0, t; }" : "=r"(a) : "l"(p));
    return a;
}
#define CP16(dst, src) \
    asm volatile("cp.async.cg.shared.global [%0], [%1], 16;" :: "r"(dst), "l"(src) : "memory")
#define CP_COMMIT() asm volatile("cp.async.commit_group;" ::: "memory")
#define CP_WAITN(n) asm volatile("cp.async.wait_group %0;" :: "n"(n) : "memory")

#define LDSM_X4(r0, r1, r2, r3, addr) \
    asm volatile("ldmatrix.sync.aligned.m8n8.x4.shared.b16 {%0,%1,%2,%3}, [%4];" \
        : "=r"(r0), "=r"(r1), "=r"(r2), "=r"(r3) : "r"(addr))

#define LDS64F(x, y, addr) \
    asm volatile("ld.shared.v2.f32 {%0,%1}, [%2];" : "=f"(x), "=f"(y) : "r"(addr))

#define MMA_F16(d, a, b0, b1) \
    asm volatile("mma.sync.aligned.m16n8k16.row.col.f32.f16.f16.f32 " \
        "{%0,%1,%2,%3}, {%4,%5,%6,%7}, {%8,%9}, {%0,%1,%2,%3};" \
        : "+f"((d)[0]), "+f"((d)[1]), "+f"((d)[2]), "+f"((d)[3]) \
        : "r"((a)[0]), "r"((a)[1]), "r"((a)[2]), "r"((a)[3]), "r"(b0), "r"(b1))

__device__ __forceinline__ uint32_t f2h2(float lo, float hi) {
    __half2 h = __floats2half2_rn(lo, hi);
    return *reinterpret_cast<uint32_t*>(&h);
}

// ---------------- prep: fp16 + transpose W via smem tiles ----------------
// Block = 32k x 32n tile, 128 threads, grid (8,16) = 128 blocks.
__global__ __launch_bounds__(128) void convert_w(const float* __restrict__ W) {
    __shared__ float tile[32][33];
    const int k0 = blockIdx.x * 32;
    const int n0 = blockIdx.y * 32;
    const int tid = threadIdx.x;

    // read: 32 k-rows x 8 float4 = 256 float4, 2 per thread (coalesced in n)
#pragma unroll
    for (int r = 0; r < 2; r++) {
        int idx = tid + r * 128;
        int k  = idx >> 3;                // 0..31
        int n4 = (idx & 7) << 2;          // 0..28
        float4 v = *reinterpret_cast<const float4*>(W + (size_t)(k0 + k) * UU + n0 + n4);
        tile[k][n4 + 0] = v.x;
        tile[k][n4 + 1] = v.y;
        tile[k][n4 + 2] = v.z;
        tile[k][n4 + 3] = v.w;
    }
    __syncthreads();

    // write: thread -> (n = tid/4, kgroup of 8 = (tid%4)*8): one 16B store
    const int n  = tid >> 2;              // 0..31
    const int kg = (tid & 3) << 3;        // 0,8,16,24
    __half2 h[4];
#pragma unroll
    for (int i = 0; i < 4; i++)
        h[i] = __floats2half2_rn(tile[kg + 2 * i][n], tile[kg + 2 * i + 1][n]);
    *reinterpret_cast<uint4*>(g_Bt + (size_t)(n0 + n) * DD + k0 + kg) =
        *reinterpret_cast<uint4*>(h);
}

// ---------------- GEMM via mma.sync (R13-proven shape) ----------------
// CTA 128(M) x 128(N), K-chunk 32, 3-stage cp.async ring, 8 warps,
// warp tile 32x64 (mt=2, nt=8) -> 16 independent accumulators innermost.
#define ROWA      160                          // bytes per A smem row (32 floats + pad)
#define ABUF      (128 * ROWA)                 // 20480 B
#define ROWB      80
#define BBUF      (128 * ROWB)                 // 10240 B
#define OFF_B     ABUF
#define STAGE_SZ  (ABUF + BBUF)                // 30720 B
#define NSTAGE    3
#define SM_TOTAL  (NSTAGE * STAGE_SZ)          // 92160 B

__device__ __forceinline__ void load_chunk(uint32_t stage_base, const char* gx,
                                           int bm, int bn, int k0, int tid) {
    const char* gB = reinterpret_cast<const char*>(g_Bt);
    // A: fp32, 128 rows x 128 B -> 1024 cp16 (4 per thread)
#pragma unroll
    for (int r = 0; r < 4; r++) {
        int idx = tid + r * 256;
        int row = idx >> 3;
        int seg = (idx & 7) << 4;
        CP16(stage_base + row * ROWA + seg,
             gx + (size_t)(bm + row) * 1024 + k0 * 4 + seg);
    }
    // B: fp16, 128 rows x 64 B -> 512 cp16 (2 per thread)
#pragma unroll
    for (int r = 0; r < 2; r++) {
        int idx = tid + r * 256;
        int row = idx >> 2;
        int seg = (idx & 3) << 4;
        CP16(stage_base + OFF_B + row * ROWB + seg,
             gB + (size_t)(bn + row) * 512 + k0 * 2 + seg);
    }
}

__global__ __launch_bounds__(256, 2) void indrnn_gemm_mma(
    const float* __restrict__ X, const float* __restrict__ bias)
{
    extern __shared__ char smem[];
    const uint32_t sbase = smem_u32(smem);
    const char* gx = reinterpret_cast<const char*>(X);
    const int tid  = threadIdx.x;
    const int wid  = tid >> 5;
    const int lane = tid & 31;
    const int bm   = blockIdx.y * 128;
    const int bn   = blockIdx.x * 128;
    const int wm   = (wid & 3) * 32;
    const int wn   = (wid >> 2) * 64;

    float acc[2][8][4];
#pragma unroll
    for (int mt = 0; mt < 2; mt++)
#pragma unroll
        for (int nt = 0; nt < 8; nt++)
#pragma unroll
            for (int i = 0; i < 4; i++) acc[mt][nt][i] = 0.0f;

    load_chunk(sbase,            gx, bm, bn, 0,  tid); CP_COMMIT();
    load_chunk(sbase + STAGE_SZ, gx, bm, bn, 32, tid); CP_COMMIT();

    // A-frag addressing (fp32 smem): row = wm + mt*16 + g (+8), col = 2t (+1, +8)
    const int g = lane >> 2;
    const int t = lane & 3;
    const uint32_t a_base = (wm + g) * ROWA + t * 8;
    const uint32_t b_base = (wn + ((lane >> 4) & 1) * 8 + (lane & 7)) * ROWB
                          + ((lane >> 3) & 1) * 16;

    int stage = 0;
    for (int c = 0; c < 8; c++) {
        if (c < 7) { CP_WAITN(1); } else { CP_WAITN(0); }
        __syncthreads();   // chunk c visible; all warps vacated stage of chunk c-1

        if (c + 2 < 8) {
            int ns = stage + 2; if (ns >= NSTAGE) ns -= NSTAGE;
            load_chunk(sbase + ns * STAGE_SZ, gx, bm, bn, (c + 2) * 32, tid);
            CP_COMMIT();
        }

        const uint32_t aSm = sbase + stage * STAGE_SZ;
        const uint32_t bSm = aSm + OFF_B;

#pragma unroll
        for (int k16 = 0; k16 < 2; k16++) {
            const uint32_t kbA = k16 * 64;
            const uint32_t kbB = k16 * 32;

            uint32_t af[2][4];
#pragma unroll
            for (int mt = 0; mt < 2; mt++) {
                const uint32_t ab = aSm + a_base + mt * (16 * ROWA) + kbA;
                float x0, y0, x1, y1, x2, y2, x3, y3;
                LDS64F(x0, y0, ab);
                LDS64F(x1, y1, ab + 8 * ROWA);
                LDS64F(x2, y2, ab + 32);
                LDS64F(x3, y3, ab + 8 * ROWA + 32);
                af[mt][0] = f2h2(x0, y0);
                af[mt][1] = f2h2(x1, y1);
                af[mt][2] = f2h2(x2, y2);
                af[mt][3] = f2h2(x3, y3);
            }

            uint32_t bf[8][2];
#pragma unroll
            for (int np = 0; np < 4; np++)
                LDSM_X4(bf[2 * np][0], bf[2 * np][1], bf[2 * np + 1][0], bf[2 * np + 1][1],
                        bSm + b_base + np * (16 * ROWB) + kbB);

            // 16 independent accumulators back-to-back
#pragma unroll
            for (int nt = 0; nt < 8; nt++) {
                MMA_F16(acc[0][nt], af[0], bf[nt][0], bf[nt][1]);
                MMA_F16(acc[1][nt], af[1], bf[nt][0], bf[nt][1]);
            }
        }

        if (++stage == NSTAGE) stage = 0;
    }

    // epilogue -> fp16 proj scratch: c-frag thread holds (m = lane/4 [+8], n = (lane%4)*2 [+1])
    const int m0   = bm + wm + (lane >> 2);
    const int col0 = bn + wn + (lane & 3) * 2;
#pragma unroll
    for (int mt = 0; mt < 2; mt++) {
#pragma unroll
        for (int nt = 0; nt < 8; nt++) {
            const int r = m0 + mt * 16;
            const int cc = col0 + nt * 8;
            const float2 bv = *reinterpret_cast<const float2*>(bias + cc);
            const uint32_t h0v = f2h2(acc[mt][nt][0] + bv.x, acc[mt][nt][1] + bv.y);
            const uint32_t h1v = f2h2(acc[mt][nt][2] + bv.x, acc[mt][nt][3] + bv.y);
            *reinterpret_cast<uint32_t*>(g_proj + (size_t)r * UU + cc)       = h0v;
            *reinterpret_cast<uint32_t*>(g_proj + (size_t)(r + 8) * UU + cc) = h1v;
        }
    }
}

// ---------------- scan: fp16 proj via cp.async smem ring -> fp32 out ----------------
#define SC_TS    16
#define SC_NS    8
#define SC_STAGE (SC_TS * 128 * 2)          // 4096 B (fp16)
#define SC_SMEM  (SC_NS * SC_STAGE)         // 32768 B

__device__ __forceinline__ void scan_issue_stage(uint32_t sm_stage, const char* gbase,
                                                 int t0, int tid) {
    // stage = 16 t-rows x 256 B -> 256 cp16, 2 per thread
#pragma unroll
    for (int k = 0; k < 2; k++) {
        int j = tid + k * 128;              // 0..255
        int t = j >> 4;                     // 0..15
        int seg = (j & 15) << 4;            // 16B chunks across 256B row
        CP16(sm_stage + t * 256 + seg, gbase + (size_t)(t0 + t) * (UU * 2) + seg);
    }
}

__global__ __launch_bounds__(128) void indrnn_scan(
    const float* __restrict__ h0,
    const float* __restrict__ u,
    float* __restrict__ out)
{
    extern __shared__ __half sbuf_h[];
    const uint32_t sm = smem_u32(sbuf_h);
    const int tid = threadIdx.x;
    const int u0  = (blockIdx.x & 3) * 128;
    const int bb  = blockIdx.x >> 2;
    const int uu  = u0 + tid;

    const float uc = fminf(fmaxf(u[uu], 0.0f), 1.0f);
    float h = h0[bb * UU + uu];

    float* pout = out + (size_t)bb * TT * UU + uu;
    const char* gbase = reinterpret_cast<const char*>(g_proj)
                      + ((size_t)bb * TT * UU + u0) * 2;

#pragma unroll
    for (int s = 0; s < SC_NS - 1; s++) {
        scan_issue_stage(sm + s * SC_STAGE, gbase, s * SC_TS, tid);
        CP_COMMIT();
    }

#pragma unroll 1
    for (int blk = 0; blk < TT / SC_TS; blk++) {
        CP_WAITN(SC_NS - 2);
        __syncthreads();

        const int nb = blk + SC_NS - 1;
        if (nb < TT / SC_TS) {
            scan_issue_stage(sm + (nb & (SC_NS - 1)) * SC_STAGE, gbase, nb * SC_TS, tid);
        }
        CP_COMMIT();

        const __half* stage = sbuf_h + (blk & (SC_NS - 1)) * (SC_TS * 128) + tid;
        const int t0 = blk * SC_TS;
#pragma unroll
        for (int i = 0; i < SC_TS; i++) {
            h = fmaxf(fmaf(h, uc, __half2float(stage[i * 128])), 0.0f);
            pout[(size_t)(t0 + i) * UU] = h;
        }
    }
}

extern "C" void kernel_launch(void* const* d_in, const int* in_sizes, int n_in,
                              void* d_out, int out_size)
{
    const float* x  = (const float*)d_in[0];
    const float* h0 = (const float*)d_in[1];
    const float* W  = (const float*)d_in[2];
    const float* u  = (const float*)d_in[3];
    const float* b  = (const float*)d_in[4];
    float* out = (float*)d_out;

    cudaFuncSetAttribute(indrnn_gemm_mma, cudaFuncAttributeMaxDynamicSharedMemorySize, SM_TOTAL);
    cudaFuncSetAttribute(indrnn_scan,     cudaFuncAttributeMaxDynamicSharedMemorySize, SC_SMEM);

    dim3 wgrid(DD / 32, UU / 32);    // (8, 16) = 128 blocks
    convert_w<<<wgrid, 128>>>(W);

    dim3 grid(UU / 128, MM / 128);   // (4, 256) = 1024 CTAs
    indrnn_gemm_mma<<<grid, 256, SM_TOTAL>>>(x, b);

    indrnn_scan<<<(BATCH * UU) / 128, 128, SC_SMEM>>>(h0, u, out);
}